// round 2
// baseline (speedup 1.0000x reference)
#include <cuda_runtime.h>
#include <cuda_bf16.h>
#include <cstdint>

// Problem constants
constexpr int Bn = 8, Sn = 2048, Dn = 2048, Rn = 512, En = 8;
constexpr int Mn = Bn * Sn;  // 16384 tokens

// Scratch (device globals: allocation-free rule)
__device__ __nv_bfloat16 g_xb[(size_t)Mn * Dn];   // 64 MB: LN'd activations, bf16
__device__ __nv_bfloat16 g_w1b[(size_t)Dn * Rn];  // 2 MB: w1 in bf16
__device__ float g_H[Bn * Rn];                    // per-batch sum of GELU outputs
__device__ float g_logits[Bn * En];

// ---------------------------------------------------------------------------
// Kernel 1: cast w1 -> bf16, zero H
// ---------------------------------------------------------------------------
__global__ void prep_kernel(const float* __restrict__ w1) {
    int idx = blockIdx.x * blockDim.x + threadIdx.x;
    if (idx < Dn * Rn) g_w1b[idx] = __float2bfloat16(w1[idx]);
    if (idx < Bn * Rn) g_H[idx] = 0.f;
}

// ---------------------------------------------------------------------------
// Kernel 2: LayerNorm per token, write bf16
// ---------------------------------------------------------------------------
__global__ void ln_kernel(const float* __restrict__ hs,
                          const float* __restrict__ gamma,
                          const float* __restrict__ beta) {
    const int token = blockIdx.x;
    const int t = threadIdx.x;  // 256 threads, 2048 elems -> 2 float4 each
    const float4* row = reinterpret_cast<const float4*>(hs + (size_t)token * Dn);
    float4 v0 = row[t];
    float4 v1 = row[t + 256];
    float s  = v0.x + v0.y + v0.z + v0.w + v1.x + v1.y + v1.z + v1.w;
    float ss = v0.x*v0.x + v0.y*v0.y + v0.z*v0.z + v0.w*v0.w
             + v1.x*v1.x + v1.y*v1.y + v1.z*v1.z + v1.w*v1.w;
    #pragma unroll
    for (int o = 16; o; o >>= 1) {
        s  += __shfl_xor_sync(0xFFFFFFFFu, s,  o);
        ss += __shfl_xor_sync(0xFFFFFFFFu, ss, o);
    }
    __shared__ float rs[8], rss[8];
    const int w = t >> 5, l = t & 31;
    if (l == 0) { rs[w] = s; rss[w] = ss; }
    __syncthreads();
    if (t < 32) {
        float a = (t < 8) ? rs[t] : 0.f;
        float c = (t < 8) ? rss[t] : 0.f;
        #pragma unroll
        for (int o = 4; o; o >>= 1) {
            a += __shfl_xor_sync(0xFFFFFFFFu, a, o);
            c += __shfl_xor_sync(0xFFFFFFFFu, c, o);
        }
        if (t == 0) { rs[0] = a; rss[0] = c; }
    }
    __syncthreads();
    const float mu   = rs[0] * (1.f / Dn);
    const float var  = rss[0] * (1.f / Dn) - mu * mu;
    const float rstd = rsqrtf(var + 1e-5f);

    const float4* g4 = reinterpret_cast<const float4*>(gamma);
    const float4* b4 = reinterpret_cast<const float4*>(beta);
    __nv_bfloat162* out2 = reinterpret_cast<__nv_bfloat162*>(g_xb + (size_t)token * Dn);

    {
        float4 g = g4[t], bb = b4[t];
        float y0 = (v0.x - mu) * rstd * g.x + bb.x;
        float y1 = (v0.y - mu) * rstd * g.y + bb.y;
        float y2 = (v0.z - mu) * rstd * g.z + bb.z;
        float y3 = (v0.w - mu) * rstd * g.w + bb.w;
        out2[2 * t]     = __floats2bfloat162_rn(y0, y1);
        out2[2 * t + 1] = __floats2bfloat162_rn(y2, y3);
    }
    {
        int t2 = t + 256;
        float4 g = g4[t2], bb = b4[t2];
        float y0 = (v1.x - mu) * rstd * g.x + bb.x;
        float y1 = (v1.y - mu) * rstd * g.y + bb.y;
        float y2 = (v1.z - mu) * rstd * g.z + bb.z;
        float y3 = (v1.w - mu) * rstd * g.w + bb.w;
        out2[2 * t2]     = __floats2bfloat162_rn(y0, y1);
        out2[2 * t2 + 1] = __floats2bfloat162_rn(y2, y3);
    }
}

// ---------------------------------------------------------------------------
// Kernel 3: GEMM (xb @ w1b) + bias + exact GELU + per-batch row reduction
// ---------------------------------------------------------------------------
constexpr int BM = 128, BN = 64, BK = 32;
constexpr int ASTR = 40;  // padded bf16 row stride (80B) -> conflict-free ldmatrix
constexpr int BSTR = 72;  // padded bf16 row stride (144B)
constexpr int A_BUF = BM * ASTR;  // elems per buffer
constexpr int B_BUF = BK * BSTR;
constexpr int SMEM_AB_BYTES = 2 * (A_BUF + B_BUF) * 2;       // 29696
constexpr int RED_STRIDE = 65;
constexpr int SMEM_RED_BYTES = BM * RED_STRIDE * 4;          // 33280
constexpr int SMEM_BYTES = (SMEM_RED_BYTES > SMEM_AB_BYTES) ? SMEM_RED_BYTES : SMEM_AB_BYTES;

__device__ __forceinline__ void cp_async16(void* smem_dst, const void* gmem_src) {
    unsigned sa = (unsigned)__cvta_generic_to_shared(smem_dst);
    asm volatile("cp.async.cg.shared.global [%0], [%1], 16;\n" :: "r"(sa), "l"(gmem_src));
}

__device__ __forceinline__ float gelu_exact(float x) {
    return 0.5f * x * (1.f + erff(x * 0.7071067811865475f));
}

__device__ __forceinline__ void mma16816(float* c, const uint32_t* a, uint32_t b0, uint32_t b1) {
    asm volatile(
        "mma.sync.aligned.m16n8k16.row.col.f32.bf16.bf16.f32 "
        "{%0,%1,%2,%3}, {%4,%5,%6,%7}, {%8,%9}, {%0,%1,%2,%3};"
        : "+f"(c[0]), "+f"(c[1]), "+f"(c[2]), "+f"(c[3])
        : "r"(a[0]), "r"(a[1]), "r"(a[2]), "r"(a[3]), "r"(b0), "r"(b1));
}

__global__ __launch_bounds__(256) void gemm_kernel(const float* __restrict__ b1) {
    __shared__ __align__(16) unsigned char smem[SMEM_BYTES];
    __nv_bfloat16* sA = reinterpret_cast<__nv_bfloat16*>(smem);
    __nv_bfloat16* sB = sA + 2 * A_BUF;
    float* red = reinterpret_cast<float*>(smem);

    const int tid = threadIdx.x;
    const int bn = blockIdx.x;   // 0..7   (N tiles)
    const int bm = blockIdx.y;   // 0..127 (M tiles)
    const int warp = tid >> 5, lane = tid & 31;
    const int wm = warp >> 1, wn = warp & 1;

    const uint32_t asBase = (uint32_t)__cvta_generic_to_shared(sA);
    const uint32_t bsBase = (uint32_t)__cvta_generic_to_shared(sB);

    float acc[2][4][4];
    #pragma unroll
    for (int i = 0; i < 2; ++i)
        #pragma unroll
        for (int j = 0; j < 4; ++j)
            #pragma unroll
            for (int k = 0; k < 4; ++k) acc[i][j][k] = 0.f;

    const int a_r = tid >> 2, a_c = (tid & 3) * 8;
    const int b_r = tid >> 3, b_c = (tid & 7) * 8;
    const __nv_bfloat16* gA0 = g_xb + (size_t)(bm * BM + a_r) * Dn + a_c;
    const __nv_bfloat16* gA1 = gA0 + (size_t)64 * Dn;
    const __nv_bfloat16* gB0 = g_w1b + (size_t)b_r * Rn + bn * BN + b_c;

    constexpr int KT = Dn / BK;  // 64 k-tiles

    // prologue load of tile 0
    {
        cp_async16(sA + a_r * ASTR + a_c, gA0);
        cp_async16(sA + (a_r + 64) * ASTR + a_c, gA1);
        cp_async16(sB + b_r * BSTR + b_c, gB0);
        asm volatile("cp.async.commit_group;\n" ::);
    }

    for (int kt = 0; kt < KT; ++kt) {
        const int buf = kt & 1;
        if (kt + 1 < KT) {
            const int nb = buf ^ 1;
            const int k0 = (kt + 1) * BK;
            cp_async16(sA + nb * A_BUF + a_r * ASTR + a_c, gA0 + k0);
            cp_async16(sA + nb * A_BUF + (a_r + 64) * ASTR + a_c, gA1 + k0);
            cp_async16(sB + nb * B_BUF + b_r * BSTR + b_c, gB0 + (size_t)k0 * Rn);
            asm volatile("cp.async.commit_group;\n" ::);
            asm volatile("cp.async.wait_group 1;\n" ::);
        } else {
            asm volatile("cp.async.wait_group 0;\n" ::);
        }
        __syncthreads();

        #pragma unroll
        for (int ks = 0; ks < BK; ks += 16) {
            uint32_t ra[2][4], rb[2][4];
            #pragma unroll
            for (int im = 0; im < 2; ++im) {
                uint32_t addr = asBase + 2u * (uint32_t)(buf * A_BUF
                              + (wm * 32 + im * 16 + (lane & 15)) * ASTR
                              + ks + ((lane >> 4) << 3));
                asm volatile("ldmatrix.sync.aligned.m8n8.x4.shared.b16 {%0,%1,%2,%3}, [%4];"
                    : "=r"(ra[im][0]), "=r"(ra[im][1]), "=r"(ra[im][2]), "=r"(ra[im][3])
                    : "r"(addr));
            }
            #pragma unroll
            for (int jn = 0; jn < 2; ++jn) {
                uint32_t addr = bsBase + 2u * (uint32_t)(buf * B_BUF
                              + (ks + (lane & 15)) * BSTR
                              + wn * 32 + jn * 16 + ((lane >> 4) << 3));
                asm volatile("ldmatrix.sync.aligned.m8n8.x4.trans.shared.b16 {%0,%1,%2,%3}, [%4];"
                    : "=r"(rb[jn][0]), "=r"(rb[jn][1]), "=r"(rb[jn][2]), "=r"(rb[jn][3])
                    : "r"(addr));
            }
            #pragma unroll
            for (int im = 0; im < 2; ++im)
                #pragma unroll
                for (int jn = 0; jn < 2; ++jn) {
                    mma16816(acc[im][jn * 2 + 0], ra[im], rb[jn][0], rb[jn][1]);
                    mma16816(acc[im][jn * 2 + 1], ra[im], rb[jn][2], rb[jn][3]);
                }
        }
        __syncthreads();
    }

    // Epilogue: +bias, GELU, stash to smem, column-reduce over BM rows
    const int g = lane >> 2, tq = lane & 3;
    const int batch = bm >> 4;  // 2048 rows per batch / 128 rows per block
    #pragma unroll
    for (int im = 0; im < 2; ++im)
        #pragma unroll
        for (int jt = 0; jt < 4; ++jt) {
            const int r0 = wm * 32 + im * 16 + g;
            const int c0 = wn * 32 + jt * 8 + tq * 2;
            const int gn = bn * BN + c0;
            const float bia0 = b1[gn], bia1 = b1[gn + 1];
            red[r0 * RED_STRIDE + c0]           = gelu_exact(acc[im][jt][0] + bia0);
            red[r0 * RED_STRIDE + c0 + 1]       = gelu_exact(acc[im][jt][1] + bia1);
            red[(r0 + 8) * RED_STRIDE + c0]     = gelu_exact(acc[im][jt][2] + bia0);
            red[(r0 + 8) * RED_STRIDE + c0 + 1] = gelu_exact(acc[im][jt][3] + bia1);
        }
    __syncthreads();
    {
        const int col = tid & 63;
        const int q = tid >> 6;  // 4 quarters of 32 rows
        float p = 0.f;
        #pragma unroll
        for (int r = 0; r < 32; ++r) p += red[(q * 32 + r) * RED_STRIDE + col];
        atomicAdd(&g_H[batch * Rn + bn * BN + col], p);
    }
}

// ---------------------------------------------------------------------------
// Kernel 4: per batch, T = H @ w2 + S*b2 ; logits = T @ wr + br
// ---------------------------------------------------------------------------
__global__ void tail_kernel(const float* __restrict__ w2, const float* __restrict__ b2,
                            const float* __restrict__ wr, const float* __restrict__ br) {
    __shared__ float sH[Rn];
    __shared__ float sT[Rn];
    const int b = blockIdx.x, t = threadIdx.x;  // 8 blocks x 512 threads
    sH[t] = g_H[b * Rn + t];
    __syncthreads();
    float acc = (float)Sn * b2[t];
    for (int r = 0; r < Rn; ++r) acc = fmaf(sH[r], w2[r * Rn + t], acc);
    sT[t] = acc;
    __syncthreads();
    if (t < En) {
        float lg = br[t];
        for (int q = 0; q < Rn; ++q) lg = fmaf(sT[q], wr[q * En + t], lg);
        g_logits[b * En + t] = lg;
    }
}

// ---------------------------------------------------------------------------
// Kernel 5: aux loss (BCE-with-logits vs one-hot argmax) + mode of argmaxes
// ---------------------------------------------------------------------------
__global__ void final_kernel(float* out, int out_size) {
    if (threadIdx.x != 0) return;
    float aux = 0.f;
    int counts[En] = {};
    for (int b = 0; b < Bn; ++b) {
        const float* l = &g_logits[b * En];
        int best = 0;
        for (int e = 1; e < En; ++e)
            if (l[e] > l[best]) best = e;  // first max (ties -> smallest idx)
        counts[best]++;
        for (int e = 0; e < En; ++e) {
            float x = l[e];
            float sp = fmaxf(x, 0.f) + log1pf(expf(-fabsf(x)));  // logaddexp(0,x)
            aux += sp - (e == best ? x : 0.f);
        }
    }
    aux *= (1.f / (Bn * En));
    int nxt = 0;
    for (int e = 1; e < En; ++e)
        if (counts[e] > counts[nxt]) nxt = e;  // first max on ties
    out[0] = aux;
    if (out_size > 1) out[1] = (float)nxt;
}

// ---------------------------------------------------------------------------
extern "C" void kernel_launch(void* const* d_in, const int* in_sizes, int n_in,
                              void* d_out, int out_size) {
    const float* hs    = (const float*)d_in[0];
    const float* gamma = (const float*)d_in[1];
    const float* beta  = (const float*)d_in[2];
    const float* w1    = (const float*)d_in[3];
    const float* b1    = (const float*)d_in[4];
    const float* w2    = (const float*)d_in[5];
    const float* b2    = (const float*)d_in[6];
    const float* wr    = (const float*)d_in[7];
    const float* br    = (const float*)d_in[8];

    prep_kernel<<<(Dn * Rn + 255) / 256, 256>>>(w1);
    ln_kernel<<<Mn, 256>>>(hs, gamma, beta);
    gemm_kernel<<<dim3(Rn / BN, Mn / BM), 256>>>(b1);
    tail_kernel<<<Bn, Rn>>>(w2, b2, wr, br);
    final_kernel<<<1, 32>>>((float*)d_out, out_size);
}